// round 7
// baseline (speedup 1.0000x reference)
#include <cuda_runtime.h>
#include <cuda_bf16.h>
#include <cstdint>

// Problem sizes (fixed)
#define B_ROWS   524288
#define TILE_M   128
#define NTILES   (B_ROWS / TILE_M)   // 4096
#define NTH      256
#define GRID     152                 // persistent CTAs, 1 per SM (GB300 = 152 SMs)
#define NTOT     320                 // [z(64) | interleaved gates i,f,g,o per j (256)]

// ---------------- SMEM layout ----------------
// W frag regions: 40 n-tiles x 8 k-steps x 32 lanes x 8 B = 81920 each
#define OFF_WHI  0
#define OFF_WLO  81920
#define OFF_A    163840              // A fp32 tile: 128 rows x 512 B = 65536
#define OFF_C    OFF_A               // c0 staging (32 KB), written AFTER frag build
#define OFF_BNC  (OFF_A + 32768)     // bounce buffers (32 KB)
#define OFF_BIAS 229376              // 320 floats
#define SMEM_BYTES 230656

// ---------------- PTX helpers (baseline ISA only — no tcgen05!) ----------------
__device__ __forceinline__ void cpa16(uint32_t dst, const void* src) {
    asm volatile("cp.async.cg.shared.global [%0], [%1], 16;" :: "r"(dst), "l"(src));
}
#define CP_COMMIT() asm volatile("cp.async.commit_group;" ::: "memory")
#define CP_WAIT0()  asm volatile("cp.async.wait_group 0;" ::: "memory")

__device__ __forceinline__ uint32_t smem_u32(const void* p) {
    uint32_t a;
    asm("{ .reg .u64 t; cvta.to.shared.u64 t, %1; cvt.u32.u64 %0, t; }" : "=r"(a) : "l"(p));
    return a;
}

__device__ __forceinline__ void mma16816(float* d, const uint32_t* a, uint32_t b0, uint32_t b1) {
    asm volatile(
        "mma.sync.aligned.m16n8k16.row.col.f32.bf16.bf16.f32 "
        "{%0,%1,%2,%3},{%4,%5,%6,%7},{%8,%9},{%0,%1,%2,%3};"
        : "+f"(d[0]), "+f"(d[1]), "+f"(d[2]), "+f"(d[3])
        : "r"(a[0]), "r"(a[1]), "r"(a[2]), "r"(a[3]), "r"(b0), "r"(b1));
}

// fp32 -> (hi bf16, lo bf16 residual), packed pairs (elem0 in low 16 bits)
__device__ __forceinline__ void split2(float x0, float x1, uint32_t& hi, uint32_t& lo) {
    __nv_bfloat16 h0 = __float2bfloat16(x0);
    __nv_bfloat16 h1 = __float2bfloat16(x1);
    __nv_bfloat16 l0 = __float2bfloat16(x0 - __bfloat162float(h0));
    __nv_bfloat16 l1 = __float2bfloat16(x1 - __bfloat162float(h1));
    hi = (uint32_t)__bfloat16_as_ushort(h0) | ((uint32_t)__bfloat16_as_ushort(h1) << 16);
    lo = (uint32_t)__bfloat16_as_ushort(l0) | ((uint32_t)__bfloat16_as_ushort(l1) << 16);
}

// Reordered weight fetch: col c<64 -> z head (W_o row c); else gate-interleaved:
// gc=c-64, j=gc/4, g=gc%4 (i,f,g,o), source row = g*64+j in stacked W_ih/W_hh.
__device__ __forceinline__ float getW(int c, int k,
                                      const float* Wo, const float* Wih, const float* Whh) {
    if (c < 64) return Wo[c * 128 + k];
    int gc = c - 64, j = gc >> 2, g = gc & 3, r = g * 64 + j;
    return (k < 64) ? Wih[r * 64 + k] : Whh[r * 64 + (k - 64)];
}

__global__ __launch_bounds__(NTH) void lstm_hmma_kernel(
    const float* __restrict__ x,   const float* __restrict__ h0,  const float* __restrict__ c0,
    const float* __restrict__ Wih, const float* __restrict__ Whh,
    const float* __restrict__ bih, const float* __restrict__ bhh,
    const float* __restrict__ Wo,  const float* __restrict__ bo,
    float* __restrict__ out)
{
    extern __shared__ __align__(16) char sm[];
    const uint32_t smb = smem_u32(sm);
    const int tid = threadIdx.x;
    const int w   = tid >> 5;
    const int l   = tid & 31;
    const int gr  = l >> 2;            // group row 0..7
    const int q   = l & 3;             // quad lane 0..3

    // ---- one-time: W -> hi/lo bf16 frags in SMEM (frag-order, conflict-free) ----
    for (int p = tid; p < 40 * 8 * 32; p += NTH) {
        int t = p >> 8, s = (p >> 5) & 7, ln = p & 31;
        int c = 8 * t + (ln >> 2);
        int k0 = 16 * s + 2 * (ln & 3);
        float w00 = getW(c, k0,     Wo, Wih, Whh);
        float w01 = getW(c, k0 + 1, Wo, Wih, Whh);
        float w10 = getW(c, k0 + 8, Wo, Wih, Whh);
        float w11 = getW(c, k0 + 9, Wo, Wih, Whh);
        uint32_t h0p, l0p, h1p, l1p;
        split2(w00, w01, h0p, l0p);   // b0: k0, k0+1
        split2(w10, w11, h1p, l1p);   // b1: k0+8, k0+9
        uint32_t base = (uint32_t)(t * 8 + s) * 256u + (uint32_t)ln * 8u;
        *reinterpret_cast<uint2*>(sm + OFF_WHI + base) = make_uint2(h0p, h1p);
        *reinterpret_cast<uint2*>(sm + OFF_WLO + base) = make_uint2(l0p, l1p);
    }
    // bias, same column reordering
    for (int c = tid; c < NTOT; c += NTH) {
        float b;
        if (c < 64) b = bo[c];
        else { int gc = c - 64, j = gc >> 2, g = gc & 3; b = bih[g * 64 + j] + bhh[g * 64 + j]; }
        reinterpret_cast<float*>(sm + OFF_BIAS)[c] = b;
    }
    __syncthreads();

    const float* bias = reinterpret_cast<const float*>(sm + OFF_BIAS);
    const int r0l = 16 * w + gr, r1l = r0l + 8;

    for (int tile = blockIdx.x; tile < NTILES; tile += gridDim.x) {
        const int row0 = tile * TILE_M;

        // ---- load A tile (x|h fp32) via cp.async into XOR-swizzled SMEM ----
        for (int p = tid; p < 4096; p += NTH) {           // 128 rows x 32 16B-chunks
            int r = p >> 5, ch = p & 31;
            uint32_t dst = smb + OFF_A + (uint32_t)r * 512u + ((uint32_t)((2 * ch) ^ ((r & 3) << 2)) << 3);
            const float* src = (ch < 16) ? (x  + (size_t)(row0 + r) * 64 + ch * 4)
                                         : (h0 + (size_t)(row0 + r) * 64 + (ch - 16) * 4);
            cpa16(dst, src);
        }
        CP_COMMIT(); CP_WAIT0();
        __syncthreads();

        // ---- build A hi/lo fragments in registers ----
        uint32_t ahi[32], alo[32];
        #pragma unroll
        for (int s = 0; s < 8; s++) {
            int c2 = 8 * s + q;
            float2 v00 = *reinterpret_cast<const float2*>(sm + OFF_A + r0l * 512 + (((c2    ) ^ ((r0l & 3) << 2)) << 3));
            float2 v01 = *reinterpret_cast<const float2*>(sm + OFF_A + r0l * 512 + (((c2 + 4) ^ ((r0l & 3) << 2)) << 3));
            float2 v10 = *reinterpret_cast<const float2*>(sm + OFF_A + r1l * 512 + (((c2    ) ^ ((r1l & 3) << 2)) << 3));
            float2 v11 = *reinterpret_cast<const float2*>(sm + OFF_A + r1l * 512 + (((c2 + 4) ^ ((r1l & 3) << 2)) << 3));
            split2(v00.x, v00.y, ahi[4 * s + 0], alo[4 * s + 0]);  // a0: row gr,  k lo
            split2(v10.x, v10.y, ahi[4 * s + 1], alo[4 * s + 1]);  // a1: row gr+8,k lo
            split2(v01.x, v01.y, ahi[4 * s + 2], alo[4 * s + 2]);  // a2: row gr,  k hi
            split2(v11.x, v11.y, ahi[4 * s + 3], alo[4 * s + 3]);  // a3: row gr+8,k hi
        }
        __syncthreads();   // A region now dead -> safe to overwrite with c0

        // ---- c0 staging (overlaps with MMA passes) ----
        for (int p = tid; p < 2048; p += NTH) {           // 128 rows x 16 16B-chunks
            int r = p >> 4, jc = p & 15;
            uint32_t dst = smb + OFF_C + (uint32_t)r * 256u + ((uint32_t)(jc ^ (r & 7)) << 4);
            cpa16(dst, c0 + (size_t)(row0 + r) * 64 + jc * 4);
        }
        CP_COMMIT();

        // ---- 5 passes of 8 n-tiles: pass0 = z head, passes 1-4 = gates ----
        for (int pass = 0; pass < 5; pass++) {
            const int tbase = pass * 8;
            float acc[32];
            #pragma unroll
            for (int i = 0; i < 32; i++) acc[i] = 0.0f;

            #pragma unroll
            for (int s = 0; s < 8; s++) {
                uint32_t bh0[8], bh1[8];
                uint32_t baseH = (uint32_t)(tbase * 8 + s) * 256u + (uint32_t)l * 8u;
                #pragma unroll
                for (int tt = 0; tt < 8; tt++) {
                    uint2 v = *reinterpret_cast<const uint2*>(sm + OFF_WHI + baseH + ((uint32_t)tt << 11));
                    bh0[tt] = v.x; bh1[tt] = v.y;
                }
                #pragma unroll
                for (int tt = 0; tt < 8; tt++)
                    mma16816(&acc[4 * tt], &ahi[4 * s], bh0[tt], bh1[tt]);     // Ahi * Whi
                #pragma unroll
                for (int tt = 0; tt < 8; tt++) {
                    uint2 v = *reinterpret_cast<const uint2*>(sm + OFF_WLO + baseH + ((uint32_t)tt << 11));
                    mma16816(&acc[4 * tt], &ahi[4 * s], v.x, v.y);             // Ahi * Wlo
                }
                #pragma unroll
                for (int tt = 0; tt < 8; tt++)
                    mma16816(&acc[4 * tt], &alo[4 * s], bh0[tt], bh1[tt]);     // Alo * Whi
            }

            if (pass == 0) {
                // ---- z head: row-wise log-softmax (reduce across quad lanes) ----
                float m0 = -1e30f, m1 = -1e30f;
                #pragma unroll
                for (int tt = 0; tt < 8; tt++) {
                    int cb = 8 * tt + 2 * q;
                    acc[4 * tt + 0] += bias[cb];     acc[4 * tt + 1] += bias[cb + 1];
                    acc[4 * tt + 2] += bias[cb];     acc[4 * tt + 3] += bias[cb + 1];
                    m0 = fmaxf(m0, fmaxf(acc[4 * tt + 0], acc[4 * tt + 1]));
                    m1 = fmaxf(m1, fmaxf(acc[4 * tt + 2], acc[4 * tt + 3]));
                }
                m0 = fmaxf(m0, __shfl_xor_sync(0xffffffffu, m0, 1));
                m0 = fmaxf(m0, __shfl_xor_sync(0xffffffffu, m0, 2));
                m1 = fmaxf(m1, __shfl_xor_sync(0xffffffffu, m1, 1));
                m1 = fmaxf(m1, __shfl_xor_sync(0xffffffffu, m1, 2));
                float s0 = 0.0f, s1 = 0.0f;
                #pragma unroll
                for (int tt = 0; tt < 8; tt++) {
                    s0 += __expf(acc[4 * tt + 0] - m0) + __expf(acc[4 * tt + 1] - m0);
                    s1 += __expf(acc[4 * tt + 2] - m1) + __expf(acc[4 * tt + 3] - m1);
                }
                s0 += __shfl_xor_sync(0xffffffffu, s0, 1);
                s0 += __shfl_xor_sync(0xffffffffu, s0, 2);
                s1 += __shfl_xor_sync(0xffffffffu, s1, 1);
                s1 += __shfl_xor_sync(0xffffffffu, s1, 2);
                float lse0 = m0 + __logf(s0), lse1 = m1 + __logf(s1);
                #pragma unroll
                for (int tt = 0; tt < 8; tt++) {
                    int cb = 8 * tt + 2 * q;
                    float2 va = make_float2(acc[4 * tt + 0] - lse0, acc[4 * tt + 1] - lse0);
                    float2 vb = make_float2(acc[4 * tt + 2] - lse1, acc[4 * tt + 3] - lse1);
                    *reinterpret_cast<float2*>(sm + OFF_BNC + r0l * 256 + ((cb ^ ((r0l & 7) << 3)) << 2)) = va;
                    *reinterpret_cast<float2*>(sm + OFF_BNC + r1l * 256 + ((cb ^ ((r1l & 7) << 3)) << 2)) = vb;
                }
                CP_WAIT0();          // c0 visible after the syncthreads below
                __syncthreads();
                for (int p = tid; p < 4096; p += NTH) {   // coalesced logp store
                    int r = p >> 5, c2 = (p & 31) << 1;
                    float2 v = *reinterpret_cast<const float2*>(sm + OFF_BNC + r * 256 + ((c2 ^ ((r & 7) << 3)) << 2));
                    *reinterpret_cast<float2*>(out + (size_t)(row0 + r) * 64 + c2) = v;
                }
                __syncthreads();
            } else {
                // ---- gates: even lanes hold (i,f), odd (g,o) of same j; pair via shfl ----
                const bool even = (q & 1) == 0;
                const float numer = even ? 1.0f : 2.0f;
                const float subv  = even ? 0.0f : 1.0f;
                const float scale = even ? -1.0f : -2.0f;
                #pragma unroll
                for (int tt = 0; tt < 8; tt++) {
                    int t = tbase + tt;
                    int cb = 8 * t + 2 * q;
                    float v0 = acc[4 * tt + 0] + bias[cb];
                    float v1 = acc[4 * tt + 1] + bias[cb + 1];
                    float v2 = acc[4 * tt + 2] + bias[cb];
                    float v3 = acc[4 * tt + 3] + bias[cb + 1];
                    // even: sigmoid(i); odd: tanh(g) = 2*sigm(2g)-1
                    float a0 = numer / (1.0f + __expf(scale * v0)) - subv;
                    float a1 = 1.0f / (1.0f + __expf(-v1));           // f or o: sigmoid either way
                    float a2 = numer / (1.0f + __expf(scale * v2)) - subv;
                    float a3 = 1.0f / (1.0f + __expf(-v3));
                    float p0 = __shfl_xor_sync(0xffffffffu, a0, 1);
                    float p1 = __shfl_xor_sync(0xffffffffu, a1, 1);
                    float p2 = __shfl_xor_sync(0xffffffffu, a2, 1);
                    float p3 = __shfl_xor_sync(0xffffffffu, a3, 1);
                    if (even) {
                        int jl = 2 * tt + (q >> 1);
                        int jg = 16 * (pass - 1) + jl;
                        float c00 = *reinterpret_cast<const float*>(sm + OFF_C + r0l * 256 + (((jg >> 2) ^ (r0l & 7)) << 4) + ((jg & 3) << 2));
                        float c11 = *reinterpret_cast<const float*>(sm + OFF_C + r1l * 256 + (((jg >> 2) ^ (r1l & 7)) << 4) + ((jg & 3) << 2));
                        float cn0 = a1 * c00 + a0 * p0;               // f*c + i*g
                        float cn1 = a3 * c11 + a2 * p2;
                        float hn0 = p1 * (2.0f / (1.0f + __expf(-2.0f * cn0)) - 1.0f);   // o*tanh(cn)
                        float hn1 = p3 * (2.0f / (1.0f + __expf(-2.0f * cn1)) - 1.0f);
                        *reinterpret_cast<float*>(sm + OFF_BNC        + r0l * 64 + ((jl ^ ((r0l & 3) << 2)) << 2)) = hn0;
                        *reinterpret_cast<float*>(sm + OFF_BNC        + r1l * 64 + ((jl ^ ((r1l & 3) << 2)) << 2)) = hn1;
                        *reinterpret_cast<float*>(sm + OFF_BNC + 8192 + r0l * 64 + ((jl ^ ((r0l & 3) << 2)) << 2)) = cn0;
                        *reinterpret_cast<float*>(sm + OFF_BNC + 8192 + r1l * 64 + ((jl ^ ((r1l & 3) << 2)) << 2)) = cn1;
                    }
                }
                __syncthreads();
                for (int p = tid; p < 2048; p += NTH) {   // coalesced h/c slice store
                    int r = p >> 4, jl = p & 15;
                    int col = 16 * (pass - 1) + jl;
                    float hv = *reinterpret_cast<const float*>(sm + OFF_BNC        + r * 64 + ((jl ^ ((r & 3) << 2)) << 2));
                    float cv = *reinterpret_cast<const float*>(sm + OFF_BNC + 8192 + r * 64 + ((jl ^ ((r & 3) << 2)) << 2));
                    size_t g = (size_t)(row0 + r) * 64 + col;
                    out[(size_t)B_ROWS * 64 + g]     = hv;
                    out[(size_t)2 * B_ROWS * 64 + g] = cv;
                }
                __syncthreads();
            }
        }
    }
}

extern "C" void kernel_launch(void* const* d_in, const int* in_sizes, int n_in,
                              void* d_out, int out_size) {
    (void)in_sizes; (void)n_in; (void)out_size;
    cudaFuncSetAttribute(lstm_hmma_kernel, cudaFuncAttributeMaxDynamicSharedMemorySize, SMEM_BYTES);
    lstm_hmma_kernel<<<GRID, NTH, SMEM_BYTES>>>(
        (const float*)d_in[0], (const float*)d_in[1], (const float*)d_in[2],
        (const float*)d_in[3], (const float*)d_in[4],
        (const float*)d_in[5], (const float*)d_in[6],
        (const float*)d_in[7], (const float*)d_in[8],
        (float*)d_out);
}

// round 10
// speedup vs baseline: 1.1168x; 1.1168x over previous
#include <cuda_runtime.h>
#include <cuda_bf16.h>
#include <cstdint>

// Problem sizes (fixed)
#define B_ROWS   524288
#define TILE_M   128
#define NTILES   (B_ROWS / TILE_M)   // 4096
#define NTH      256
#define GRID     152                 // persistent CTAs, 1 per SM (GB300 = 152 SMs)
#define NTOT     320                 // [z(64) | interleaved gates i,f,g,o per j (256)]

// ---------------- SMEM layout ----------------
// W frag regions: 40 n-tiles x 8 k-steps x 32 lanes x 8 B = 81920 each
#define OFF_WHI  0
#define OFF_WLO  81920
#define OFF_C    163840              // c0 / c_new (in-place): 128 rows x 256 B = 32 KB
#define OFF_H    196608              // h_new staging: 128 rows x 256 B = 32 KB
#define OFF_BIAS 229376              // 320 floats
#define SMEM_BYTES 230656

// ---------------- PTX helpers (baseline ISA only — no tcgen05!) ----------------
__device__ __forceinline__ void cpa16(uint32_t dst, const void* src) {
    asm volatile("cp.async.cg.shared.global [%0], [%1], 16;" :: "r"(dst), "l"(src));
}
#define CP_COMMIT() asm volatile("cp.async.commit_group;" ::: "memory")
#define CP_WAIT0()  asm volatile("cp.async.wait_group 0;" ::: "memory")

__device__ __forceinline__ uint32_t smem_u32(const void* p) {
    uint32_t a;
    asm("{ .reg .u64 t; cvta.to.shared.u64 t, %1; cvt.u32.u64 %0, t; }" : "=r"(a) : "l"(p));
    return a;
}

__device__ __forceinline__ void mma16816(float* d, const uint32_t* a, uint32_t b0, uint32_t b1) {
    asm volatile(
        "mma.sync.aligned.m16n8k16.row.col.f32.bf16.bf16.f32 "
        "{%0,%1,%2,%3},{%4,%5,%6,%7},{%8,%9},{%0,%1,%2,%3};"
        : "+f"(d[0]), "+f"(d[1]), "+f"(d[2]), "+f"(d[3])
        : "r"(a[0]), "r"(a[1]), "r"(a[2]), "r"(a[3]), "r"(b0), "r"(b1));
}

// fp32 -> (hi bf16, lo bf16 residual), packed pairs (elem0 in low 16 bits)
__device__ __forceinline__ void split2(float x0, float x1, uint32_t& hi, uint32_t& lo) {
    __nv_bfloat16 h0 = __float2bfloat16(x0);
    __nv_bfloat16 h1 = __float2bfloat16(x1);
    __nv_bfloat16 l0 = __float2bfloat16(x0 - __bfloat162float(h0));
    __nv_bfloat16 l1 = __float2bfloat16(x1 - __bfloat162float(h1));
    hi = (uint32_t)__bfloat16_as_ushort(h0) | ((uint32_t)__bfloat16_as_ushort(h1) << 16);
    lo = (uint32_t)__bfloat16_as_ushort(l0) | ((uint32_t)__bfloat16_as_ushort(l1) << 16);
}

// Reordered weight fetch: col c<64 -> z head (W_o row c); else gate-interleaved:
// gc=c-64, j=gc/4, g=gc%4 (i,f,g,o), source row = g*64+j in stacked W_ih/W_hh.
__device__ __forceinline__ float getW(int c, int k,
                                      const float* Wo, const float* Wih, const float* Whh) {
    if (c < 64) return Wo[c * 128 + k];
    int gc = c - 64, j = gc >> 2, g = gc & 3, r = g * 64 + j;
    return (k < 64) ? Wih[r * 64 + k] : Whh[r * 64 + (k - 64)];
}

__global__ __launch_bounds__(NTH, 1) void lstm_hmma_kernel(
    const float* __restrict__ x,   const float* __restrict__ h0,  const float* __restrict__ c0,
    const float* __restrict__ Wih, const float* __restrict__ Whh,
    const float* __restrict__ bih, const float* __restrict__ bhh,
    const float* __restrict__ Wo,  const float* __restrict__ bo,
    float* __restrict__ out)
{
    extern __shared__ __align__(16) char sm[];
    const uint32_t smb = smem_u32(sm);
    const int tid = threadIdx.x;
    const int w   = tid >> 5;
    const int l   = tid & 31;
    const int gr  = l >> 2;            // group row 0..7
    const int q   = l & 3;             // quad lane 0..3

    // ---- one-time: W -> hi/lo bf16 frags in SMEM (frag-order, conflict-free) ----
    for (int p = tid; p < 40 * 8 * 32; p += NTH) {
        int t = p >> 8, s = (p >> 5) & 7, ln = p & 31;
        int c = 8 * t + (ln >> 2);
        int k0 = 16 * s + 2 * (ln & 3);
        float w00 = getW(c, k0,     Wo, Wih, Whh);
        float w01 = getW(c, k0 + 1, Wo, Wih, Whh);
        float w10 = getW(c, k0 + 8, Wo, Wih, Whh);
        float w11 = getW(c, k0 + 9, Wo, Wih, Whh);
        uint32_t h0p, l0p, h1p, l1p;
        split2(w00, w01, h0p, l0p);   // b0: k0, k0+1
        split2(w10, w11, h1p, l1p);   // b1: k0+8, k0+9
        uint32_t base = (uint32_t)(t * 8 + s) * 256u + (uint32_t)ln * 8u;
        *reinterpret_cast<uint2*>(sm + OFF_WHI + base) = make_uint2(h0p, h1p);
        *reinterpret_cast<uint2*>(sm + OFF_WLO + base) = make_uint2(l0p, l1p);
    }
    // bias, same column reordering
    for (int c = tid; c < NTOT; c += NTH) {
        float b;
        if (c < 64) b = bo[c];
        else { int gc = c - 64, j = gc >> 2, g = gc & 3; b = bih[g * 64 + j] + bhh[g * 64 + j]; }
        reinterpret_cast<float*>(sm + OFF_BIAS)[c] = b;
    }
    __syncthreads();

    const float* bias = reinterpret_cast<const float*>(sm + OFF_BIAS);
    const int r0l = 16 * w + gr, r1l = r0l + 8;

    for (int tile = blockIdx.x; tile < NTILES; tile += gridDim.x) {
        const int row0 = tile * TILE_M;

        // ---- c0: each warp cp.asyncs ONLY its own 16 rows (warp-local completion) ----
        #pragma unroll
        for (int i = 0; i < 8; i++) {
            int ci = i * 32 + l;                       // 0..255 within warp's block
            int r  = 16 * w + (ci >> 4);
            int jc = ci & 15;
            uint32_t dst = smb + OFF_C + (uint32_t)r * 256u + ((uint32_t)(jc ^ (r & 7)) << 4);
            cpa16(dst, c0 + (size_t)(row0 + r) * 64 + jc * 4);
        }
        CP_COMMIT();

        // ---- A tile: direct LDG -> registers (sector-perfect per quad), no SMEM ----
        uint32_t ahi[32], alo[32];
        #pragma unroll
        for (int s = 0; s < 8; s++) {
            const float* bp = (s < 4) ? x : h0;
            int kf2 = 8 * (s & 3) + q;                 // float2 index within the 32-float2 row
            const float2* p0 = reinterpret_cast<const float2*>(bp) + (size_t)(row0 + r0l) * 32 + kf2;
            const float2* p1 = reinterpret_cast<const float2*>(bp) + (size_t)(row0 + r1l) * 32 + kf2;
            float2 v00 = p0[0], v01 = p0[4];
            float2 v10 = p1[0], v11 = p1[4];
            split2(v00.x, v00.y, ahi[4 * s + 0], alo[4 * s + 0]);  // a0: row gr,  k lo
            split2(v10.x, v10.y, ahi[4 * s + 1], alo[4 * s + 1]);  // a1: row gr+8,k lo
            split2(v01.x, v01.y, ahi[4 * s + 2], alo[4 * s + 2]);  // a2: row gr,  k hi
            split2(v11.x, v11.y, ahi[4 * s + 3], alo[4 * s + 3]);  // a3: row gr+8,k hi
        }

        // ---- 5 passes of 8 n-tiles: pass0 = z head, passes 1-4 = gates. NO BARRIERS. ----
        for (int pass = 0; pass < 5; pass++) {
            const int tbase = pass * 8;
            float acc[32];
            #pragma unroll
            for (int i = 0; i < 32; i++) acc[i] = 0.0f;

            #pragma unroll
            for (int s = 0; s < 8; s++) {
                uint32_t bh0[8], bh1[8];
                uint32_t baseH = (uint32_t)(tbase * 8 + s) * 256u + (uint32_t)l * 8u;
                #pragma unroll
                for (int tt = 0; tt < 8; tt++) {
                    uint2 v = *reinterpret_cast<const uint2*>(sm + OFF_WHI + baseH + ((uint32_t)tt << 11));
                    bh0[tt] = v.x; bh1[tt] = v.y;
                }
                #pragma unroll
                for (int tt = 0; tt < 8; tt++)
                    mma16816(&acc[4 * tt], &ahi[4 * s], bh0[tt], bh1[tt]);     // Ahi * Whi
                #pragma unroll
                for (int tt = 0; tt < 8; tt++) {
                    uint2 v = *reinterpret_cast<const uint2*>(sm + OFF_WLO + baseH + ((uint32_t)tt << 11));
                    mma16816(&acc[4 * tt], &ahi[4 * s], v.x, v.y);             // Ahi * Wlo
                }
                #pragma unroll
                for (int tt = 0; tt < 8; tt++)
                    mma16816(&acc[4 * tt], &alo[4 * s], bh0[tt], bh1[tt]);     // Alo * Whi
            }

            if (pass == 0) {
                // ---- z head: row-wise log-softmax, stored DIRECTLY to gmem (32B sectors) ----
                float m0 = -1e30f, m1 = -1e30f;
                #pragma unroll
                for (int tt = 0; tt < 8; tt++) {
                    int cb = 8 * tt + 2 * q;
                    acc[4 * tt + 0] += bias[cb];     acc[4 * tt + 1] += bias[cb + 1];
                    acc[4 * tt + 2] += bias[cb];     acc[4 * tt + 3] += bias[cb + 1];
                    m0 = fmaxf(m0, fmaxf(acc[4 * tt + 0], acc[4 * tt + 1]));
                    m1 = fmaxf(m1, fmaxf(acc[4 * tt + 2], acc[4 * tt + 3]));
                }
                m0 = fmaxf(m0, __shfl_xor_sync(0xffffffffu, m0, 1));
                m0 = fmaxf(m0, __shfl_xor_sync(0xffffffffu, m0, 2));
                m1 = fmaxf(m1, __shfl_xor_sync(0xffffffffu, m1, 1));
                m1 = fmaxf(m1, __shfl_xor_sync(0xffffffffu, m1, 2));
                float s0 = 0.0f, s1 = 0.0f;
                #pragma unroll
                for (int tt = 0; tt < 8; tt++) {
                    s0 += __expf(acc[4 * tt + 0] - m0) + __expf(acc[4 * tt + 1] - m0);
                    s1 += __expf(acc[4 * tt + 2] - m1) + __expf(acc[4 * tt + 3] - m1);
                }
                s0 += __shfl_xor_sync(0xffffffffu, s0, 1);
                s0 += __shfl_xor_sync(0xffffffffu, s0, 2);
                s1 += __shfl_xor_sync(0xffffffffu, s1, 1);
                s1 += __shfl_xor_sync(0xffffffffu, s1, 2);
                float lse0 = m0 + __logf(s0), lse1 = m1 + __logf(s1);
                #pragma unroll
                for (int tt = 0; tt < 8; tt++) {
                    int cb = 8 * tt + 2 * q;
                    float2 va = make_float2(acc[4 * tt + 0] - lse0, acc[4 * tt + 1] - lse0);
                    float2 vb = make_float2(acc[4 * tt + 2] - lse1, acc[4 * tt + 3] - lse1);
                    *reinterpret_cast<float2*>(out + (size_t)(row0 + r0l) * 64 + cb) = va;
                    *reinterpret_cast<float2*>(out + (size_t)(row0 + r1l) * 64 + cb) = vb;
                }
                // c0 for THIS warp's rows is needed starting pass 1:
                CP_WAIT0();
                __syncwarp();
            } else {
                // ---- gates: even lanes hold (i,f), odd (g,o) of same j; pair via shfl ----
                const bool even = (q & 1) == 0;
                const float numer = even ? 1.0f : 2.0f;
                const float subv  = even ? 0.0f : 1.0f;
                const float scale = even ? -1.0f : -2.0f;
                #pragma unroll
                for (int tt = 0; tt < 8; tt++) {
                    int t = tbase + tt;
                    int cb = 8 * t + 2 * q;
                    float v0 = acc[4 * tt + 0] + bias[cb];
                    float v1 = acc[4 * tt + 1] + bias[cb + 1];
                    float v2 = acc[4 * tt + 2] + bias[cb];
                    float v3 = acc[4 * tt + 3] + bias[cb + 1];
                    // even: sigmoid(i); odd: tanh(g) = 2*sigm(2g)-1
                    float a0 = numer / (1.0f + __expf(scale * v0)) - subv;
                    float a1 = 1.0f / (1.0f + __expf(-v1));           // f or o: sigmoid either way
                    float a2 = numer / (1.0f + __expf(scale * v2)) - subv;
                    float a3 = 1.0f / (1.0f + __expf(-v3));
                    float p0 = __shfl_xor_sync(0xffffffffu, a0, 1);
                    float p1 = __shfl_xor_sync(0xffffffffu, a1, 1);
                    float p2 = __shfl_xor_sync(0xffffffffu, a2, 1);
                    float p3 = __shfl_xor_sync(0xffffffffu, a3, 1);
                    if (even) {
                        int jg = 16 * (pass - 1) + 2 * tt + (q >> 1);   // global col 0..63
                        uint32_t co0 = (uint32_t)r0l * 256u + ((uint32_t)((jg >> 2) ^ (r0l & 7)) << 4) + ((uint32_t)(jg & 3) << 2);
                        uint32_t co1 = (uint32_t)r1l * 256u + ((uint32_t)((jg >> 2) ^ (r1l & 7)) << 4) + ((uint32_t)(jg & 3) << 2);
                        float c00 = *reinterpret_cast<const float*>(sm + OFF_C + co0);
                        float c11 = *reinterpret_cast<const float*>(sm + OFF_C + co1);
                        float cn0 = a1 * c00 + a0 * p0;               // f*c + i*g
                        float cn1 = a3 * c11 + a2 * p2;
                        float hn0 = p1 * (2.0f / (1.0f + __expf(-2.0f * cn0)) - 1.0f);   // o*tanh(cn)
                        float hn1 = p3 * (2.0f / (1.0f + __expf(-2.0f * cn1)) - 1.0f);
                        *reinterpret_cast<float*>(sm + OFF_C + co0) = cn0;   // c_new in place
                        *reinterpret_cast<float*>(sm + OFF_C + co1) = cn1;
                        *reinterpret_cast<float*>(sm + OFF_H + co0) = hn0;
                        *reinterpret_cast<float*>(sm + OFF_H + co1) = hn1;
                    }
                }
            }
        }

        // ---- one barrier, then fully vectorized h/c stores ----
        __syncthreads();
        #pragma unroll
        for (int i = 0; i < 8; i++) {
            int p = tid + i * NTH;                     // 0..2047
            int r = p >> 4, c4 = p & 15;
            uint32_t off = (uint32_t)r * 256u + ((uint32_t)(c4 ^ (r & 7)) << 4);
            float4 hv = *reinterpret_cast<const float4*>(sm + OFF_H + off);
            float4 cv = *reinterpret_cast<const float4*>(sm + OFF_C + off);
            size_t g = (size_t)(row0 + r) * 64 + (size_t)c4 * 4;
            *reinterpret_cast<float4*>(out + (size_t)B_ROWS * 64 + g)     = hv;
            *reinterpret_cast<float4*>(out + (size_t)2 * B_ROWS * 64 + g) = cv;
        }
        __syncthreads();   // protect OFF_C/OFF_H before next tile's cp.async / writes
    }
}

extern "C" void kernel_launch(void* const* d_in, const int* in_sizes, int n_in,
                              void* d_out, int out_size) {
    (void)in_sizes; (void)n_in; (void)out_size;
    cudaFuncSetAttribute(lstm_hmma_kernel, cudaFuncAttributeMaxDynamicSharedMemorySize, SMEM_BYTES);
    lstm_hmma_kernel<<<GRID, NTH, SMEM_BYTES>>>(
        (const float*)d_in[0], (const float*)d_in[1], (const float*)d_in[2],
        (const float*)d_in[3], (const float*)d_in[4],
        (const float*)d_in[5], (const float*)d_in[6],
        (const float*)d_in[7], (const float*)d_in[8],
        (float*)d_out);
}

// round 12
// speedup vs baseline: 1.1512x; 1.0308x over previous
#include <cuda_runtime.h>
#include <cuda_bf16.h>
#include <cstdint>

// Problem sizes (fixed)
#define B_ROWS   524288
#define TILE_M   128
#define NTILES   (B_ROWS / TILE_M)   // 4096
#define NTH      512                 // 16 warps: pairs split the n-dimension
#define GRID     152                 // persistent CTAs, 1 per SM (GB300 = 152 SMs)
#define NTOT     320                 // [z(64) | interleaved gates i,f,g,o per j (256)]

// ---------------- SMEM layout ----------------
// W frag regions: 40 n-tiles x 8 k-steps x 32 lanes x 8 B = 81920 each
#define OFF_WHI  0
#define OFF_WLO  81920
#define OFF_H    163840              // h_new staging: 128 rows x 256 B = 32 KB
#define OFF_CN   196608              // c_new staging: 32 KB
#define OFF_BIAS 229376              // 320 floats
#define SMEM_BYTES 230656

__device__ __forceinline__ uint32_t smem_u32(const void* p) {
    uint32_t a;
    asm("{ .reg .u64 t; cvta.to.shared.u64 t, %1; cvt.u32.u64 %0, t; }" : "=r"(a) : "l"(p));
    return a;
}

__device__ __forceinline__ void mma16816(float* d, const uint32_t* a, uint32_t b0, uint32_t b1) {
    asm volatile(
        "mma.sync.aligned.m16n8k16.row.col.f32.bf16.bf16.f32 "
        "{%0,%1,%2,%3},{%4,%5,%6,%7},{%8,%9},{%0,%1,%2,%3};"
        : "+f"(d[0]), "+f"(d[1]), "+f"(d[2]), "+f"(d[3])
        : "r"(a[0]), "r"(a[1]), "r"(a[2]), "r"(a[3]), "r"(b0), "r"(b1));
}

// fp32 -> (hi bf16, lo bf16 residual), packed pairs (elem0 in low 16 bits)
__device__ __forceinline__ void split2(float x0, float x1, uint32_t& hi, uint32_t& lo) {
    __nv_bfloat16 h0 = __float2bfloat16(x0);
    __nv_bfloat16 h1 = __float2bfloat16(x1);
    __nv_bfloat16 l0 = __float2bfloat16(x0 - __bfloat162float(h0));
    __nv_bfloat16 l1 = __float2bfloat16(x1 - __bfloat162float(h1));
    hi = (uint32_t)__bfloat16_as_ushort(h0) | ((uint32_t)__bfloat16_as_ushort(h1) << 16);
    lo = (uint32_t)__bfloat16_as_ushort(l0) | ((uint32_t)__bfloat16_as_ushort(l1) << 16);
}

// Reordered weight fetch: col c<64 -> z head (W_o row c); else gate-interleaved:
// gc=c-64, j=gc/4, g=gc%4 (i,f,g,o), source row = g*64+j in stacked W_ih/W_hh.
__device__ __forceinline__ float getW(int c, int k,
                                      const float* Wo, const float* Wih, const float* Whh) {
    if (c < 64) return Wo[c * 128 + k];
    int gc = c - 64, j = gc >> 2, g = gc & 3, r = g * 64 + j;
    return (k < 64) ? Wih[r * 64 + k] : Whh[r * 64 + (k - 64)];
}

// One pass: NT n-tiles starting at global tile tbase. IS_Z = z-head (log-softmax
// + direct gmem store); else gate tiles (LSTM pointwise, stage h/c in SMEM).
template<int NT, bool IS_Z>
__device__ __forceinline__ void do_pass(
    int tbase, char* sm, const float* __restrict__ bias,
    const uint32_t* ahi, const uint32_t* alo,
    int r0l, int r1l, int q, int l, int row0,
    float* __restrict__ out, const float* __restrict__ c0)
{
    float acc[4 * NT];
    #pragma unroll
    for (int i = 0; i < 4 * NT; i++) acc[i] = 0.0f;

    #pragma unroll
    for (int s = 0; s < 8; s++) {
        uint32_t bh0[NT], bh1[NT];
        uint32_t baseH = (uint32_t)(tbase * 8 + s) * 256u + (uint32_t)l * 8u;
        #pragma unroll
        for (int tt = 0; tt < NT; tt++) {
            uint2 v = *reinterpret_cast<const uint2*>(sm + OFF_WHI + baseH + ((uint32_t)tt << 11));
            bh0[tt] = v.x; bh1[tt] = v.y;
        }
        #pragma unroll
        for (int tt = 0; tt < NT; tt++)
            mma16816(&acc[4 * tt], &ahi[4 * s], bh0[tt], bh1[tt]);     // Ahi * Whi
        #pragma unroll
        for (int tt = 0; tt < NT; tt++) {
            uint2 v = *reinterpret_cast<const uint2*>(sm + OFF_WLO + baseH + ((uint32_t)tt << 11));
            mma16816(&acc[4 * tt], &ahi[4 * s], v.x, v.y);             // Ahi * Wlo
        }
        #pragma unroll
        for (int tt = 0; tt < NT; tt++)
            mma16816(&acc[4 * tt], &alo[4 * s], bh0[tt], bh1[tt]);     // Alo * Whi
    }

    if (IS_Z) {
        // ---- z head: row-wise log-softmax, stored DIRECTLY to gmem (32B sectors) ----
        float m0 = -1e30f, m1 = -1e30f;
        #pragma unroll
        for (int tt = 0; tt < NT; tt++) {
            int cb = 8 * (tbase + tt) + 2 * q;
            acc[4 * tt + 0] += bias[cb];     acc[4 * tt + 1] += bias[cb + 1];
            acc[4 * tt + 2] += bias[cb];     acc[4 * tt + 3] += bias[cb + 1];
            m0 = fmaxf(m0, fmaxf(acc[4 * tt + 0], acc[4 * tt + 1]));
            m1 = fmaxf(m1, fmaxf(acc[4 * tt + 2], acc[4 * tt + 3]));
        }
        m0 = fmaxf(m0, __shfl_xor_sync(0xffffffffu, m0, 1));
        m0 = fmaxf(m0, __shfl_xor_sync(0xffffffffu, m0, 2));
        m1 = fmaxf(m1, __shfl_xor_sync(0xffffffffu, m1, 1));
        m1 = fmaxf(m1, __shfl_xor_sync(0xffffffffu, m1, 2));
        float s0 = 0.0f, s1 = 0.0f;
        #pragma unroll
        for (int tt = 0; tt < NT; tt++) {
            s0 += __expf(acc[4 * tt + 0] - m0) + __expf(acc[4 * tt + 1] - m0);
            s1 += __expf(acc[4 * tt + 2] - m1) + __expf(acc[4 * tt + 3] - m1);
        }
        s0 += __shfl_xor_sync(0xffffffffu, s0, 1);
        s0 += __shfl_xor_sync(0xffffffffu, s0, 2);
        s1 += __shfl_xor_sync(0xffffffffu, s1, 1);
        s1 += __shfl_xor_sync(0xffffffffu, s1, 2);
        float lse0 = m0 + __logf(s0), lse1 = m1 + __logf(s1);
        #pragma unroll
        for (int tt = 0; tt < NT; tt++) {
            int cb = 8 * (tbase + tt) + 2 * q;
            float2 va = make_float2(acc[4 * tt + 0] - lse0, acc[4 * tt + 1] - lse0);
            float2 vb = make_float2(acc[4 * tt + 2] - lse1, acc[4 * tt + 3] - lse1);
            *reinterpret_cast<float2*>(out + (size_t)(row0 + r0l) * 64 + cb) = va;
            *reinterpret_cast<float2*>(out + (size_t)(row0 + r1l) * 64 + cb) = vb;
        }
    } else {
        // ---- gates: even lanes hold (i,f), odd (g,o) of same j; pair via shfl ----
        const bool even = (q & 1) == 0;
        const float numer = even ? 1.0f : 2.0f;
        const float subv  = even ? 0.0f : 1.0f;
        const float scale = even ? -1.0f : -2.0f;
        #pragma unroll
        for (int tt = 0; tt < NT; tt++) {
            int t  = tbase + tt;
            int cb = 8 * t + 2 * q;
            float v0 = acc[4 * tt + 0] + bias[cb];
            float v1 = acc[4 * tt + 1] + bias[cb + 1];
            float v2 = acc[4 * tt + 2] + bias[cb];
            float v3 = acc[4 * tt + 3] + bias[cb + 1];
            // even: sigmoid(i); odd: tanh(g) = 2*sigm(2g)-1
            float a0 = numer / (1.0f + __expf(scale * v0)) - subv;
            float a1 = 1.0f / (1.0f + __expf(-v1));           // f or o: sigmoid either way
            float a2 = numer / (1.0f + __expf(scale * v2)) - subv;
            float a3 = 1.0f / (1.0f + __expf(-v3));
            float p0 = __shfl_xor_sync(0xffffffffu, a0, 1);
            float p1 = __shfl_xor_sync(0xffffffffu, a1, 1);
            float p2 = __shfl_xor_sync(0xffffffffu, a2, 1);
            float p3 = __shfl_xor_sync(0xffffffffu, a3, 1);
            if (even) {
                int jg = 2 * (t - 8) + (q >> 1);              // global col 0..63
                float c00 = c0[(size_t)(row0 + r0l) * 64 + jg];   // direct LDG (L1-friendly)
                float c11 = c0[(size_t)(row0 + r1l) * 64 + jg];
                float cn0 = a1 * c00 + a0 * p0;               // f*c + i*g
                float cn1 = a3 * c11 + a2 * p2;
                float hn0 = p1 * (2.0f / (1.0f + __expf(-2.0f * cn0)) - 1.0f);   // o*tanh(cn)
                float hn1 = p3 * (2.0f / (1.0f + __expf(-2.0f * cn1)) - 1.0f);
                uint32_t co0 = (uint32_t)r0l * 256u + ((uint32_t)((jg >> 2) ^ (r0l & 7)) << 4) + ((uint32_t)(jg & 3) << 2);
                uint32_t co1 = (uint32_t)r1l * 256u + ((uint32_t)((jg >> 2) ^ (r1l & 7)) << 4) + ((uint32_t)(jg & 3) << 2);
                *reinterpret_cast<float*>(sm + OFF_CN + co0) = cn0;
                *reinterpret_cast<float*>(sm + OFF_CN + co1) = cn1;
                *reinterpret_cast<float*>(sm + OFF_H  + co0) = hn0;
                *reinterpret_cast<float*>(sm + OFF_H  + co1) = hn1;
            }
        }
    }
}

__global__ __launch_bounds__(NTH, 1) void lstm_hmma_kernel(
    const float* __restrict__ x,   const float* __restrict__ h0,  const float* __restrict__ c0,
    const float* __restrict__ Wih, const float* __restrict__ Whh,
    const float* __restrict__ bih, const float* __restrict__ bhh,
    const float* __restrict__ Wo,  const float* __restrict__ bo,
    float* __restrict__ out)
{
    extern __shared__ __align__(16) char sm[];
    const int tid = threadIdx.x;
    const int w    = tid >> 5;
    const int l    = tid & 31;
    const int rg   = w & 7;            // row group 0..7 (16 rows each)
    const int half = w >> 3;           // n-half: 0 = z+gates j0..23, 1 = gates j24..63
    const int gr   = l >> 2;           // group row 0..7
    const int q    = l & 3;            // quad lane 0..3

    // ---- one-time: W -> hi/lo bf16 frags in SMEM (frag-order, conflict-free) ----
    for (int p = tid; p < 40 * 8 * 32; p += NTH) {
        int t = p >> 8, s = (p >> 5) & 7, ln = p & 31;
        int c = 8 * t + (ln >> 2);
        int k0 = 16 * s + 2 * (ln & 3);
        float w00 = getW(c, k0,     Wo, Wih, Whh);
        float w01 = getW(c, k0 + 1, Wo, Wih, Whh);
        float w10 = getW(c, k0 + 8, Wo, Wih, Whh);
        float w11 = getW(c, k0 + 9, Wo, Wih, Whh);
        uint32_t h0p, l0p, h1p, l1p;
        split2(w00, w01, h0p, l0p);   // b0: k0, k0+1
        split2(w10, w11, h1p, l1p);   // b1: k0+8, k0+9
        uint32_t base = (uint32_t)(t * 8 + s) * 256u + (uint32_t)ln * 8u;
        *reinterpret_cast<uint2*>(sm + OFF_WHI + base) = make_uint2(h0p, h1p);
        *reinterpret_cast<uint2*>(sm + OFF_WLO + base) = make_uint2(l0p, l1p);
    }
    // bias, same column reordering
    for (int c = tid; c < NTOT; c += NTH) {
        float b;
        if (c < 64) b = bo[c];
        else { int gc = c - 64, j = gc >> 2, g = gc & 3; b = bih[g * 64 + j] + bhh[g * 64 + j]; }
        reinterpret_cast<float*>(sm + OFF_BIAS)[c] = b;
    }
    __syncthreads();

    const float* bias = reinterpret_cast<const float*>(sm + OFF_BIAS);
    const int r0l = 16 * rg + gr, r1l = r0l + 8;

    for (int tile = blockIdx.x; tile < NTILES; tile += gridDim.x) {
        const int row0 = tile * TILE_M;

        // ---- A tile: direct LDG -> registers (sector-perfect per quad), no SMEM ----
        uint32_t ahi[32], alo[32];
        #pragma unroll
        for (int s = 0; s < 8; s++) {
            const float* bp = (s < 4) ? x : h0;
            int kf2 = 8 * (s & 3) + q;                 // float2 index within the 32-float2 row
            const float2* p0 = reinterpret_cast<const float2*>(bp) + (size_t)(row0 + r0l) * 32 + kf2;
            const float2* p1 = reinterpret_cast<const float2*>(bp) + (size_t)(row0 + r1l) * 32 + kf2;
            float2 v00 = p0[0], v01 = p0[4];
            float2 v10 = p1[0], v11 = p1[4];
            split2(v00.x, v00.y, ahi[4 * s + 0], alo[4 * s + 0]);  // a0: row gr,  k lo
            split2(v10.x, v10.y, ahi[4 * s + 1], alo[4 * s + 1]);  // a1: row gr+8,k lo
            split2(v01.x, v01.y, ahi[4 * s + 2], alo[4 * s + 2]);  // a2: row gr,  k hi
            split2(v11.x, v11.y, ahi[4 * s + 3], alo[4 * s + 3]);  // a3: row gr+8,k hi
        }

        // ---- warp-pair n-split: half0 = z + gates j0..23, half1 = gates j24..63 ----
        if (half == 0) {
            do_pass<8, true >(0,  sm, bias, ahi, alo, r0l, r1l, q, l, row0, out, c0);
            do_pass<8, false>(8,  sm, bias, ahi, alo, r0l, r1l, q, l, row0, out, c0);
            do_pass<4, false>(16, sm, bias, ahi, alo, r0l, r1l, q, l, row0, out, c0);
        } else {
            do_pass<8, false>(20, sm, bias, ahi, alo, r0l, r1l, q, l, row0, out, c0);
            do_pass<8, false>(28, sm, bias, ahi, alo, r0l, r1l, q, l, row0, out, c0);
            do_pass<4, false>(36, sm, bias, ahi, alo, r0l, r1l, q, l, row0, out, c0);
        }

        // ---- one barrier, then fully vectorized h/c stores ----
        __syncthreads();
        #pragma unroll
        for (int i = 0; i < 4; i++) {
            int p = tid + i * NTH;                     // 0..2047
            int r = p >> 4, c4 = p & 15;
            uint32_t off = (uint32_t)r * 256u + ((uint32_t)(c4 ^ (r & 7)) << 4);
            float4 hv = *reinterpret_cast<const float4*>(sm + OFF_H  + off);
            float4 cv = *reinterpret_cast<const float4*>(sm + OFF_CN + off);
            size_t g = (size_t)(row0 + r) * 64 + (size_t)c4 * 4;
            *reinterpret_cast<float4*>(out + (size_t)B_ROWS * 64 + g)     = hv;
            *reinterpret_cast<float4*>(out + (size_t)2 * B_ROWS * 64 + g) = cv;
        }
        __syncthreads();   // protect OFF_H/OFF_CN before next tile's writes
    }
}

extern "C" void kernel_launch(void* const* d_in, const int* in_sizes, int n_in,
                              void* d_out, int out_size) {
    (void)in_sizes; (void)n_in; (void)out_size;
    cudaFuncSetAttribute(lstm_hmma_kernel, cudaFuncAttributeMaxDynamicSharedMemorySize, SMEM_BYTES);
    lstm_hmma_kernel<<<GRID, NTH, SMEM_BYTES>>>(
        (const float*)d_in[0], (const float*)d_in[1], (const float*)d_in[2],
        (const float*)d_in[3], (const float*)d_in[4],
        (const float*)d_in[5], (const float*)d_in[6],
        (const float*)d_in[7], (const float*)d_in[8],
        (float*)d_out);
}

// round 13
// speedup vs baseline: 1.2070x; 1.0485x over previous
#include <cuda_runtime.h>
#include <cuda_bf16.h>
#include <cstdint>

// Problem sizes (fixed)
#define B_ROWS   524288
#define TILE_M   128
#define NTILES   (B_ROWS / TILE_M)   // 4096
#define NTH      512                 // 16 warps: pairs split the n-dimension
#define GRID     152                 // persistent CTAs, 1 per SM (GB300 = 152 SMs)
#define NTOT     320                 // [z(64) | interleaved gates i,f,g,o per j (256)]

// ---------------- SMEM layout ----------------
// W frag regions: 40 n-tiles x 8 k-steps x 32 lanes x 8 B = 81920 each
#define OFF_WHI  0
#define OFF_WLO  81920
#define OFF_H    163840              // h_new staging: 128 rows x 256 B = 32 KB
#define OFF_CN   196608              // c_new staging: 32 KB
#define OFF_BIAS 229376              // 320 floats
#define SMEM_BYTES 230656

__device__ __forceinline__ void mma16816(float* d, const uint32_t* a, uint32_t b0, uint32_t b1) {
    asm volatile(
        "mma.sync.aligned.m16n8k16.row.col.f32.bf16.bf16.f32 "
        "{%0,%1,%2,%3},{%4,%5,%6,%7},{%8,%9},{%0,%1,%2,%3};"
        : "+f"(d[0]), "+f"(d[1]), "+f"(d[2]), "+f"(d[3])
        : "r"(a[0]), "r"(a[1]), "r"(a[2]), "r"(a[3]), "r"(b0), "r"(b1));
}

// fp32 -> (hi bf16, lo bf16 residual), packed pairs (elem0 in low 16 bits)
__device__ __forceinline__ void split2(float x0, float x1, uint32_t& hi, uint32_t& lo) {
    __nv_bfloat16 h0 = __float2bfloat16(x0);
    __nv_bfloat16 h1 = __float2bfloat16(x1);
    __nv_bfloat16 l0 = __float2bfloat16(x0 - __bfloat162float(h0));
    __nv_bfloat16 l1 = __float2bfloat16(x1 - __bfloat162float(h1));
    hi = (uint32_t)__bfloat16_as_ushort(h0) | ((uint32_t)__bfloat16_as_ushort(h1) << 16);
    lo = (uint32_t)__bfloat16_as_ushort(l0) | ((uint32_t)__bfloat16_as_ushort(l1) << 16);
}

// Reordered weight fetch: col c<64 -> z head (W_o row c); else gate-interleaved:
// gc=c-64, j=gc/4, g=gc%4 (i,f,g,o), source row = g*64+j in stacked W_ih/W_hh.
__device__ __forceinline__ float getW(int c, int k,
                                      const float* Wo, const float* Wih, const float* Whh) {
    if (c < 64) return Wo[c * 128 + k];
    int gc = c - 64, j = gc >> 2, g = gc & 3, r = g * 64 + j;
    return (k < 64) ? Wih[r * 64 + k] : Whh[r * 64 + (k - 64)];
}

// ---------------- z-head pass (NT=8, single-buffer; unchanged numerics) ----------------
__device__ __forceinline__ void do_pass_z(
    char* sm, const float* __restrict__ bias,
    const uint32_t* ahi, const uint32_t* alo,
    int r0l, int r1l, int q, int l, int row0,
    float* __restrict__ out)
{
    float acc[32];
    #pragma unroll
    for (int i = 0; i < 32; i++) acc[i] = 0.0f;

    #pragma unroll
    for (int s = 0; s < 8; s++) {
        uint32_t bh0[8], bh1[8];
        uint32_t baseH = (uint32_t)s * 256u + (uint32_t)l * 8u;
        #pragma unroll
        for (int tt = 0; tt < 8; tt++) {
            uint2 v = *reinterpret_cast<const uint2*>(sm + OFF_WHI + baseH + ((uint32_t)tt << 11));
            bh0[tt] = v.x; bh1[tt] = v.y;
        }
        #pragma unroll
        for (int tt = 0; tt < 8; tt++)
            mma16816(&acc[4 * tt], &ahi[4 * s], bh0[tt], bh1[tt]);
        #pragma unroll
        for (int tt = 0; tt < 8; tt++) {
            uint2 v = *reinterpret_cast<const uint2*>(sm + OFF_WLO + baseH + ((uint32_t)tt << 11));
            mma16816(&acc[4 * tt], &ahi[4 * s], v.x, v.y);
        }
        #pragma unroll
        for (int tt = 0; tt < 8; tt++)
            mma16816(&acc[4 * tt], &alo[4 * s], bh0[tt], bh1[tt]);
    }

    float m0 = -1e30f, m1 = -1e30f;
    #pragma unroll
    for (int tt = 0; tt < 8; tt++) {
        int cb = 8 * tt + 2 * q;
        acc[4 * tt + 0] += bias[cb];     acc[4 * tt + 1] += bias[cb + 1];
        acc[4 * tt + 2] += bias[cb];     acc[4 * tt + 3] += bias[cb + 1];
        m0 = fmaxf(m0, fmaxf(acc[4 * tt + 0], acc[4 * tt + 1]));
        m1 = fmaxf(m1, fmaxf(acc[4 * tt + 2], acc[4 * tt + 3]));
    }
    m0 = fmaxf(m0, __shfl_xor_sync(0xffffffffu, m0, 1));
    m0 = fmaxf(m0, __shfl_xor_sync(0xffffffffu, m0, 2));
    m1 = fmaxf(m1, __shfl_xor_sync(0xffffffffu, m1, 1));
    m1 = fmaxf(m1, __shfl_xor_sync(0xffffffffu, m1, 2));
    float s0 = 0.0f, s1 = 0.0f;
    #pragma unroll
    for (int tt = 0; tt < 8; tt++) {
        s0 += __expf(acc[4 * tt + 0] - m0) + __expf(acc[4 * tt + 1] - m0);
        s1 += __expf(acc[4 * tt + 2] - m1) + __expf(acc[4 * tt + 3] - m1);
    }
    s0 += __shfl_xor_sync(0xffffffffu, s0, 1);
    s0 += __shfl_xor_sync(0xffffffffu, s0, 2);
    s1 += __shfl_xor_sync(0xffffffffu, s1, 1);
    s1 += __shfl_xor_sync(0xffffffffu, s1, 2);
    float lse0 = m0 + __logf(s0), lse1 = m1 + __logf(s1);
    #pragma unroll
    for (int tt = 0; tt < 8; tt++) {
        int cb = 8 * tt + 2 * q;
        float2 va = make_float2(acc[4 * tt + 0] - lse0, acc[4 * tt + 1] - lse0);
        float2 vb = make_float2(acc[4 * tt + 2] - lse1, acc[4 * tt + 3] - lse1);
        *reinterpret_cast<float2*>(out + (size_t)(row0 + r0l) * 64 + cb) = va;
        *reinterpret_cast<float2*>(out + (size_t)(row0 + r1l) * 64 + cb) = vb;
    }
}

// ---------------- gate pass (NT=4, double-buffered W-frag prefetch) ----------------
__device__ __forceinline__ void do_pass_g4(
    int tbase, char* sm, const float* __restrict__ bias,
    const uint32_t* ahi, const uint32_t* alo,
    int r0l, int r1l, int q, int l, int row0,
    float* __restrict__ out, const float* __restrict__ c0)
{
    float acc[16];
    #pragma unroll
    for (int i = 0; i < 16; i++) acc[i] = 0.0f;

    uint32_t wh0[2][4], wh1[2][4], wl0[2][4], wl1[2][4];
    const uint32_t base0 = (uint32_t)(tbase * 8) * 256u + (uint32_t)l * 8u;

    // prefetch s=0
    #pragma unroll
    for (int tt = 0; tt < 4; tt++) {
        uint2 vh = *reinterpret_cast<const uint2*>(sm + OFF_WHI + base0 + ((uint32_t)tt << 11));
        uint2 vl = *reinterpret_cast<const uint2*>(sm + OFF_WLO + base0 + ((uint32_t)tt << 11));
        wh0[0][tt] = vh.x; wh1[0][tt] = vh.y;
        wl0[0][tt] = vl.x; wl1[0][tt] = vl.y;
    }

    #pragma unroll
    for (int s = 0; s < 8; s++) {
        const int cur = s & 1, nxt = cur ^ 1;
        if (s < 7) {                                  // prefetch s+1 while s computes
            uint32_t baseN = base0 + (uint32_t)(s + 1) * 256u;
            #pragma unroll
            for (int tt = 0; tt < 4; tt++) {
                uint2 vh = *reinterpret_cast<const uint2*>(sm + OFF_WHI + baseN + ((uint32_t)tt << 11));
                uint2 vl = *reinterpret_cast<const uint2*>(sm + OFF_WLO + baseN + ((uint32_t)tt << 11));
                wh0[nxt][tt] = vh.x; wh1[nxt][tt] = vh.y;
                wl0[nxt][tt] = vl.x; wl1[nxt][tt] = vl.y;
            }
        }
        #pragma unroll
        for (int tt = 0; tt < 4; tt++)
            mma16816(&acc[4 * tt], &ahi[4 * s], wh0[cur][tt], wh1[cur][tt]);   // Ahi*Whi
        #pragma unroll
        for (int tt = 0; tt < 4; tt++)
            mma16816(&acc[4 * tt], &ahi[4 * s], wl0[cur][tt], wl1[cur][tt]);   // Ahi*Wlo
        #pragma unroll
        for (int tt = 0; tt < 4; tt++)
            mma16816(&acc[4 * tt], &alo[4 * s], wh0[cur][tt], wh1[cur][tt]);   // Alo*Whi
    }

    // ---- gates: even lanes hold (i,f), odd (g,o) of same j; pair via shfl ----
    const bool even = ((q & 1) == 0);
    const float numer = even ? 1.0f : 2.0f;
    const float subv  = even ? 0.0f : 1.0f;
    const float scale = even ? -1.0f : -2.0f;
    #pragma unroll
    for (int tt = 0; tt < 4; tt++) {
        int t  = tbase + tt;
        int cb = 8 * t + 2 * q;
        float v0 = acc[4 * tt + 0] + bias[cb];
        float v1 = acc[4 * tt + 1] + bias[cb + 1];
        float v2 = acc[4 * tt + 2] + bias[cb];
        float v3 = acc[4 * tt + 3] + bias[cb + 1];
        float a0 = numer / (1.0f + __expf(scale * v0)) - subv;
        float a1 = 1.0f / (1.0f + __expf(-v1));
        float a2 = numer / (1.0f + __expf(scale * v2)) - subv;
        float a3 = 1.0f / (1.0f + __expf(-v3));
        float p0 = __shfl_xor_sync(0xffffffffu, a0, 1);
        float p1 = __shfl_xor_sync(0xffffffffu, a1, 1);
        float p2 = __shfl_xor_sync(0xffffffffu, a2, 1);
        float p3 = __shfl_xor_sync(0xffffffffu, a3, 1);
        if (even) {
            int jg = 2 * (t - 8) + (q >> 1);              // global col 0..63
            float c00 = c0[(size_t)(row0 + r0l) * 64 + jg];
            float c11 = c0[(size_t)(row0 + r1l) * 64 + jg];
            float cn0 = a1 * c00 + a0 * p0;               // f*c + i*g
            float cn1 = a3 * c11 + a2 * p2;
            float hn0 = p1 * (2.0f / (1.0f + __expf(-2.0f * cn0)) - 1.0f);   // o*tanh(cn)
            float hn1 = p3 * (2.0f / (1.0f + __expf(-2.0f * cn1)) - 1.0f);
            uint32_t co0 = (uint32_t)r0l * 256u + ((uint32_t)((jg >> 2) ^ (r0l & 7)) << 4) + ((uint32_t)(jg & 3) << 2);
            uint32_t co1 = (uint32_t)r1l * 256u + ((uint32_t)((jg >> 2) ^ (r1l & 7)) << 4) + ((uint32_t)(jg & 3) << 2);
            *reinterpret_cast<float*>(sm + OFF_CN + co0) = cn0;
            *reinterpret_cast<float*>(sm + OFF_CN + co1) = cn1;
            *reinterpret_cast<float*>(sm + OFF_H  + co0) = hn0;
            *reinterpret_cast<float*>(sm + OFF_H  + co1) = hn1;
        }
    }
}

__global__ __launch_bounds__(NTH, 1) void lstm_hmma_kernel(
    const float* __restrict__ x,   const float* __restrict__ h0,  const float* __restrict__ c0,
    const float* __restrict__ Wih, const float* __restrict__ Whh,
    const float* __restrict__ bih, const float* __restrict__ bhh,
    const float* __restrict__ Wo,  const float* __restrict__ bo,
    float* __restrict__ out)
{
    extern __shared__ __align__(16) char sm[];
    const int tid = threadIdx.x;
    const int w    = tid >> 5;
    const int l    = tid & 31;
    const int rg   = w & 7;            // row group 0..7 (16 rows each)
    const int half = w >> 3;           // n-half: 0 = z+gates j0..23, 1 = gates j24..63
    const int gr   = l >> 2;           // group row 0..7
    const int q    = l & 3;            // quad lane 0..3

    // ---- one-time: W -> hi/lo bf16 frags in SMEM (frag-order, conflict-free) ----
    for (int p = tid; p < 40 * 8 * 32; p += NTH) {
        int t = p >> 8, s = (p >> 5) & 7, ln = p & 31;
        int c = 8 * t + (ln >> 2);
        int k0 = 16 * s + 2 * (ln & 3);
        float w00 = getW(c, k0,     Wo, Wih, Whh);
        float w01 = getW(c, k0 + 1, Wo, Wih, Whh);
        float w10 = getW(c, k0 + 8, Wo, Wih, Whh);
        float w11 = getW(c, k0 + 9, Wo, Wih, Whh);
        uint32_t h0p, l0p, h1p, l1p;
        split2(w00, w01, h0p, l0p);   // b0: k0, k0+1
        split2(w10, w11, h1p, l1p);   // b1: k0+8, k0+9
        uint32_t base = (uint32_t)(t * 8 + s) * 256u + (uint32_t)ln * 8u;
        *reinterpret_cast<uint2*>(sm + OFF_WHI + base) = make_uint2(h0p, h1p);
        *reinterpret_cast<uint2*>(sm + OFF_WLO + base) = make_uint2(l0p, l1p);
    }
    // bias, same column reordering
    for (int c = tid; c < NTOT; c += NTH) {
        float b;
        if (c < 64) b = bo[c];
        else { int gc = c - 64, j = gc >> 2, g = gc & 3; b = bih[g * 64 + j] + bhh[g * 64 + j]; }
        reinterpret_cast<float*>(sm + OFF_BIAS)[c] = b;
    }
    __syncthreads();

    const float* bias = reinterpret_cast<const float*>(sm + OFF_BIAS);
    const int r0l = 16 * rg + gr, r1l = r0l + 8;

    for (int tile = blockIdx.x; tile < NTILES; tile += gridDim.x) {
        const int row0 = tile * TILE_M;

        // ---- A tile: direct LDG -> registers (sector-perfect per quad), no SMEM ----
        uint32_t ahi[32], alo[32];
        #pragma unroll
        for (int s = 0; s < 8; s++) {
            const float* bp = (s < 4) ? x : h0;
            int kf2 = 8 * (s & 3) + q;                 // float2 index within the 32-float2 row
            const float2* p0 = reinterpret_cast<const float2*>(bp) + (size_t)(row0 + r0l) * 32 + kf2;
            const float2* p1 = reinterpret_cast<const float2*>(bp) + (size_t)(row0 + r1l) * 32 + kf2;
            float2 v00 = p0[0], v01 = p0[4];
            float2 v10 = p1[0], v11 = p1[4];
            split2(v00.x, v00.y, ahi[4 * s + 0], alo[4 * s + 0]);  // a0: row gr,  k lo
            split2(v10.x, v10.y, ahi[4 * s + 1], alo[4 * s + 1]);  // a1: row gr+8,k lo
            split2(v01.x, v01.y, ahi[4 * s + 2], alo[4 * s + 2]);  // a2: row gr,  k hi
            split2(v11.x, v11.y, ahi[4 * s + 3], alo[4 * s + 3]);  // a3: row gr+8,k hi
        }

        // ---- warp-pair n-split: half0 = z + gates j0..23, half1 = gates j24..63 ----
        if (half == 0) {
            do_pass_z(sm, bias, ahi, alo, r0l, r1l, q, l, row0, out);
            do_pass_g4(8,  sm, bias, ahi, alo, r0l, r1l, q, l, row0, out, c0);
            do_pass_g4(12, sm, bias, ahi, alo, r0l, r1l, q, l, row0, out, c0);
            do_pass_g4(16, sm, bias, ahi, alo, r0l, r1l, q, l, row0, out, c0);
        } else {
            do_pass_g4(20, sm, bias, ahi, alo, r0l, r1l, q, l, row0, out, c0);
            do_pass_g4(24, sm, bias, ahi, alo, r0l, r1l, q, l, row0, out, c0);
            do_pass_g4(28, sm, bias, ahi, alo, r0l, r1l, q, l, row0, out, c0);
            do_pass_g4(32, sm, bias, ahi, alo, r0l, r1l, q, l, row0, out, c0);
            do_pass_g4(36, sm, bias, ahi, alo, r0l, r1l, q, l, row0, out, c0);
        }

        // ---- one barrier, then fully vectorized h/c stores ----
        __syncthreads();
        #pragma unroll
        for (int i = 0; i < 4; i++) {
            int p = tid + i * NTH;                     // 0..2047
            int r = p >> 4, c4 = p & 15;
            uint32_t off = (uint32_t)r * 256u + ((uint32_t)(c4 ^ (r & 7)) << 4);
            float4 hv = *reinterpret_cast<const float4*>(sm + OFF_H  + off);
            float4 cv = *reinterpret_cast<const float4*>(sm + OFF_CN + off);
            size_t g = (size_t)(row0 + r) * 64 + (size_t)c4 * 4;
            *reinterpret_cast<float4*>(out + (size_t)B_ROWS * 64 + g)     = hv;
            *reinterpret_cast<float4*>(out + (size_t)2 * B_ROWS * 64 + g) = cv;
        }
        __syncthreads();   // protect OFF_H/OFF_CN before next tile's writes
    }
}

extern "C" void kernel_launch(void* const* d_in, const int* in_sizes, int n_in,
                              void* d_out, int out_size) {
    (void)in_sizes; (void)n_in; (void)out_size;
    cudaFuncSetAttribute(lstm_hmma_kernel, cudaFuncAttributeMaxDynamicSharedMemorySize, SMEM_BYTES);
    lstm_hmma_kernel<<<GRID, NTH, SMEM_BYTES>>>(
        (const float*)d_in[0], (const float*)d_in[1], (const float*)d_in[2],
        (const float*)d_in[3], (const float*)d_in[4],
        (const float*)d_in[5], (const float*)d_in[6],
        (const float*)d_in[7], (const float*)d_in[8],
        (float*)d_out);
}

// round 14
// speedup vs baseline: 1.2730x; 1.0547x over previous
#include <cuda_runtime.h>
#include <cuda_bf16.h>
#include <cstdint>

// Problem sizes (fixed)
#define B_ROWS   524288
#define TILE_M   128
#define NTILES   (B_ROWS / TILE_M)   // 4096
#define NTH      512                 // 16 warps: pairs split the n-dimension
#define GRID     152                 // persistent CTAs, 1 per SM (GB300 = 152 SMs)
#define NTOT     320                 // [z(64) | interleaved gates i,f,g,o per j (256)]

// ---------------- SMEM layout ----------------
// W frag regions: 40 n-tiles x 8 k-steps x 32 lanes x 8 B = 81920 each
#define OFF_WHI  0
#define OFF_WLO  81920
#define OFF_C    163840              // c0 staged -> c_new in place: 128 rows x 256 B = 32 KB
#define OFF_H    196608              // h_new staging: 32 KB
#define OFF_BIAS 229376              // 320 floats
#define SMEM_BYTES 230656

__device__ __forceinline__ void cpa16(uint32_t dst, const void* src) {
    asm volatile("cp.async.cg.shared.global [%0], [%1], 16;" :: "r"(dst), "l"(src));
}
#define CP_COMMIT() asm volatile("cp.async.commit_group;" ::: "memory")
#define CP_WAIT0()  asm volatile("cp.async.wait_group 0;" ::: "memory")

__device__ __forceinline__ uint32_t smem_u32(const void* p) {
    uint32_t a;
    asm("{ .reg .u64 t; cvta.to.shared.u64 t, %1; cvt.u32.u64 %0, t; }" : "=r"(a) : "l"(p));
    return a;
}

__device__ __forceinline__ void mma16816(float* d, const uint32_t* a, uint32_t b0, uint32_t b1) {
    asm volatile(
        "mma.sync.aligned.m16n8k16.row.col.f32.bf16.bf16.f32 "
        "{%0,%1,%2,%3},{%4,%5,%6,%7},{%8,%9},{%0,%1,%2,%3};"
        : "+f"(d[0]), "+f"(d[1]), "+f"(d[2]), "+f"(d[3])
        : "r"(a[0]), "r"(a[1]), "r"(a[2]), "r"(a[3]), "r"(b0), "r"(b1));
}

// fp32 -> (hi bf16, lo bf16 residual), packed pairs (elem0 in low 16 bits)
__device__ __forceinline__ void split2(float x0, float x1, uint32_t& hi, uint32_t& lo) {
    __nv_bfloat16 h0 = __float2bfloat16(x0);
    __nv_bfloat16 h1 = __float2bfloat16(x1);
    __nv_bfloat16 l0 = __float2bfloat16(x0 - __bfloat162float(h0));
    __nv_bfloat16 l1 = __float2bfloat16(x1 - __bfloat162float(h1));
    hi = (uint32_t)__bfloat16_as_ushort(h0) | ((uint32_t)__bfloat16_as_ushort(h1) << 16);
    lo = (uint32_t)__bfloat16_as_ushort(l0) | ((uint32_t)__bfloat16_as_ushort(l1) << 16);
}

// Reordered weight fetch: col c<64 -> z head (W_o row c); else gate-interleaved:
// gc=c-64, j=gc/4, g=gc%4 (i,f,g,o), source row = g*64+j in stacked W_ih/W_hh.
__device__ __forceinline__ float getW(int c, int k,
                                      const float* Wo, const float* Wih, const float* Whh) {
    if (c < 64) return Wo[c * 128 + k];
    int gc = c - 64, j = gc >> 2, g = gc & 3, r = g * 64 + j;
    return (k < 64) ? Wih[r * 64 + k] : Whh[r * 64 + (k - 64)];
}

// ---------------- z-head pass (NT=8, single-buffer; unchanged numerics) ----------------
__device__ __forceinline__ void do_pass_z(
    char* sm, const float* __restrict__ bias,
    const uint32_t* ahi, const uint32_t* alo,
    int r0l, int r1l, int q, int l, int row0,
    float* __restrict__ out)
{
    float acc[32];
    #pragma unroll
    for (int i = 0; i < 32; i++) acc[i] = 0.0f;

    #pragma unroll
    for (int s = 0; s < 8; s++) {
        uint32_t bh0[8], bh1[8];
        uint32_t baseH = (uint32_t)s * 256u + (uint32_t)l * 8u;
        #pragma unroll
        for (int tt = 0; tt < 8; tt++) {
            uint2 v = *reinterpret_cast<const uint2*>(sm + OFF_WHI + baseH + ((uint32_t)tt << 11));
            bh0[tt] = v.x; bh1[tt] = v.y;
        }
        #pragma unroll
        for (int tt = 0; tt < 8; tt++)
            mma16816(&acc[4 * tt], &ahi[4 * s], bh0[tt], bh1[tt]);
        #pragma unroll
        for (int tt = 0; tt < 8; tt++) {
            uint2 v = *reinterpret_cast<const uint2*>(sm + OFF_WLO + baseH + ((uint32_t)tt << 11));
            mma16816(&acc[4 * tt], &ahi[4 * s], v.x, v.y);
        }
        #pragma unroll
        for (int tt = 0; tt < 8; tt++)
            mma16816(&acc[4 * tt], &alo[4 * s], bh0[tt], bh1[tt]);
    }

    float m0 = -1e30f, m1 = -1e30f;
    #pragma unroll
    for (int tt = 0; tt < 8; tt++) {
        int cb = 8 * tt + 2 * q;
        acc[4 * tt + 0] += bias[cb];     acc[4 * tt + 1] += bias[cb + 1];
        acc[4 * tt + 2] += bias[cb];     acc[4 * tt + 3] += bias[cb + 1];
        m0 = fmaxf(m0, fmaxf(acc[4 * tt + 0], acc[4 * tt + 1]));
        m1 = fmaxf(m1, fmaxf(acc[4 * tt + 2], acc[4 * tt + 3]));
    }
    m0 = fmaxf(m0, __shfl_xor_sync(0xffffffffu, m0, 1));
    m0 = fmaxf(m0, __shfl_xor_sync(0xffffffffu, m0, 2));
    m1 = fmaxf(m1, __shfl_xor_sync(0xffffffffu, m1, 1));
    m1 = fmaxf(m1, __shfl_xor_sync(0xffffffffu, m1, 2));
    float s0 = 0.0f, s1 = 0.0f;
    #pragma unroll
    for (int tt = 0; tt < 8; tt++) {
        s0 += __expf(acc[4 * tt + 0] - m0) + __expf(acc[4 * tt + 1] - m0);
        s1 += __expf(acc[4 * tt + 2] - m1) + __expf(acc[4 * tt + 3] - m1);
    }
    s0 += __shfl_xor_sync(0xffffffffu, s0, 1);
    s0 += __shfl_xor_sync(0xffffffffu, s0, 2);
    s1 += __shfl_xor_sync(0xffffffffu, s1, 1);
    s1 += __shfl_xor_sync(0xffffffffu, s1, 2);
    float lse0 = m0 + __logf(s0), lse1 = m1 + __logf(s1);
    #pragma unroll
    for (int tt = 0; tt < 8; tt++) {
        int cb = 8 * tt + 2 * q;
        float2 va = make_float2(acc[4 * tt + 0] - lse0, acc[4 * tt + 1] - lse0);
        float2 vb = make_float2(acc[4 * tt + 2] - lse1, acc[4 * tt + 3] - lse1);
        *reinterpret_cast<float2*>(out + (size_t)(row0 + r0l) * 64 + cb) = va;
        *reinterpret_cast<float2*>(out + (size_t)(row0 + r1l) * 64 + cb) = vb;
    }
}

// ---------------- gate pass (NT=4, double-buffered W-frag prefetch; c0 from SMEM) ----------------
__device__ __forceinline__ void do_pass_g4(
    int tbase, char* sm, const float* __restrict__ bias,
    const uint32_t* ahi, const uint32_t* alo,
    int r0l, int r1l, int q, int l)
{
    float acc[16];
    #pragma unroll
    for (int i = 0; i < 16; i++) acc[i] = 0.0f;

    uint32_t wh0[2][4], wh1[2][4], wl0[2][4], wl1[2][4];
    const uint32_t base0 = (uint32_t)(tbase * 8) * 256u + (uint32_t)l * 8u;

    // prefetch s=0
    #pragma unroll
    for (int tt = 0; tt < 4; tt++) {
        uint2 vh = *reinterpret_cast<const uint2*>(sm + OFF_WHI + base0 + ((uint32_t)tt << 11));
        uint2 vl = *reinterpret_cast<const uint2*>(sm + OFF_WLO + base0 + ((uint32_t)tt << 11));
        wh0[0][tt] = vh.x; wh1[0][tt] = vh.y;
        wl0[0][tt] = vl.x; wl1[0][tt] = vl.y;
    }

    #pragma unroll
    for (int s = 0; s < 8; s++) {
        const int cur = s & 1, nxt = cur ^ 1;
        if (s < 7) {                                  // prefetch s+1 while s computes
            uint32_t baseN = base0 + (uint32_t)(s + 1) * 256u;
            #pragma unroll
            for (int tt = 0; tt < 4; tt++) {
                uint2 vh = *reinterpret_cast<const uint2*>(sm + OFF_WHI + baseN + ((uint32_t)tt << 11));
                uint2 vl = *reinterpret_cast<const uint2*>(sm + OFF_WLO + baseN + ((uint32_t)tt << 11));
                wh0[nxt][tt] = vh.x; wh1[nxt][tt] = vh.y;
                wl0[nxt][tt] = vl.x; wl1[nxt][tt] = vl.y;
            }
        }
        #pragma unroll
        for (int tt = 0; tt < 4; tt++)
            mma16816(&acc[4 * tt], &ahi[4 * s], wh0[cur][tt], wh1[cur][tt]);   // Ahi*Whi
        #pragma unroll
        for (int tt = 0; tt < 4; tt++)
            mma16816(&acc[4 * tt], &ahi[4 * s], wl0[cur][tt], wl1[cur][tt]);   // Ahi*Wlo
        #pragma unroll
        for (int tt = 0; tt < 4; tt++)
            mma16816(&acc[4 * tt], &alo[4 * s], wh0[cur][tt], wh1[cur][tt]);   // Alo*Whi
    }

    // ---- gates: even lanes hold (i,f), odd (g,o) of same j; pair via shfl ----
    const bool even = ((q & 1) == 0);
    const float numer = even ? 1.0f : 2.0f;
    const float subv  = even ? 0.0f : 1.0f;
    const float scale = even ? -1.0f : -2.0f;
    #pragma unroll
    for (int tt = 0; tt < 4; tt++) {
        int t  = tbase + tt;
        int cb = 8 * t + 2 * q;
        float v0 = acc[4 * tt + 0] + bias[cb];
        float v1 = acc[4 * tt + 1] + bias[cb + 1];
        float v2 = acc[4 * tt + 2] + bias[cb];
        float v3 = acc[4 * tt + 3] + bias[cb + 1];
        float a0 = numer / (1.0f + __expf(scale * v0)) - subv;
        float a1 = 1.0f / (1.0f + __expf(-v1));
        float a2 = numer / (1.0f + __expf(scale * v2)) - subv;
        float a3 = 1.0f / (1.0f + __expf(-v3));
        float p0 = __shfl_xor_sync(0xffffffffu, a0, 1);
        float p1 = __shfl_xor_sync(0xffffffffu, a1, 1);
        float p2 = __shfl_xor_sync(0xffffffffu, a2, 1);
        float p3 = __shfl_xor_sync(0xffffffffu, a3, 1);
        if (even) {
            int jg = 2 * (t - 8) + (q >> 1);              // global col 0..63
            uint32_t co0 = (uint32_t)r0l * 256u + ((uint32_t)((jg >> 2) ^ (r0l & 7)) << 4) + ((uint32_t)(jg & 3) << 2);
            uint32_t co1 = (uint32_t)r1l * 256u + ((uint32_t)((jg >> 2) ^ (r1l & 7)) << 4) + ((uint32_t)(jg & 3) << 2);
            float c00 = *reinterpret_cast<const float*>(sm + OFF_C + co0);    // staged c0 (SMEM)
            float c11 = *reinterpret_cast<const float*>(sm + OFF_C + co1);
            float cn0 = a1 * c00 + a0 * p0;               // f*c + i*g
            float cn1 = a3 * c11 + a2 * p2;
            float hn0 = p1 * (2.0f / (1.0f + __expf(-2.0f * cn0)) - 1.0f);   // o*tanh(cn)
            float hn1 = p3 * (2.0f / (1.0f + __expf(-2.0f * cn1)) - 1.0f);
            *reinterpret_cast<float*>(sm + OFF_C + co0) = cn0;   // c_new in place
            *reinterpret_cast<float*>(sm + OFF_C + co1) = cn1;
            *reinterpret_cast<float*>(sm + OFF_H + co0) = hn0;
            *reinterpret_cast<float*>(sm + OFF_H + co1) = hn1;
        }
    }
}

__global__ __launch_bounds__(NTH, 1) void lstm_hmma_kernel(
    const float* __restrict__ x,   const float* __restrict__ h0,  const float* __restrict__ c0,
    const float* __restrict__ Wih, const float* __restrict__ Whh,
    const float* __restrict__ bih, const float* __restrict__ bhh,
    const float* __restrict__ Wo,  const float* __restrict__ bo,
    float* __restrict__ out)
{
    extern __shared__ __align__(16) char sm[];
    const uint32_t smb = smem_u32(sm);
    const int tid = threadIdx.x;
    const int w    = tid >> 5;
    const int l    = tid & 31;
    const int rg   = w & 7;            // row group 0..7 (16 rows each)
    const int half = w >> 3;           // n-half: 0 = z+gates j0..23, 1 = gates j24..63
    const int gr   = l >> 2;           // group row 0..7
    const int q    = l & 3;            // quad lane 0..3

    // ---- one-time: W -> hi/lo bf16 frags in SMEM (frag-order, conflict-free) ----
    for (int p = tid; p < 40 * 8 * 32; p += NTH) {
        int t = p >> 8, s = (p >> 5) & 7, ln = p & 31;
        int c = 8 * t + (ln >> 2);
        int k0 = 16 * s + 2 * (ln & 3);
        float w00 = getW(c, k0,     Wo, Wih, Whh);
        float w01 = getW(c, k0 + 1, Wo, Wih, Whh);
        float w10 = getW(c, k0 + 8, Wo, Wih, Whh);
        float w11 = getW(c, k0 + 9, Wo, Wih, Whh);
        uint32_t h0p, l0p, h1p, l1p;
        split2(w00, w01, h0p, l0p);   // b0: k0, k0+1
        split2(w10, w11, h1p, l1p);   // b1: k0+8, k0+9
        uint32_t base = (uint32_t)(t * 8 + s) * 256u + (uint32_t)ln * 8u;
        *reinterpret_cast<uint2*>(sm + OFF_WHI + base) = make_uint2(h0p, h1p);
        *reinterpret_cast<uint2*>(sm + OFF_WLO + base) = make_uint2(l0p, l1p);
    }
    // bias, same column reordering
    for (int c = tid; c < NTOT; c += NTH) {
        float b;
        if (c < 64) b = bo[c];
        else { int gc = c - 64, j = gc >> 2, g = gc & 3; b = bih[g * 64 + j] + bhh[g * 64 + j]; }
        reinterpret_cast<float*>(sm + OFF_BIAS)[c] = b;
    }
    __syncthreads();

    const float* bias = reinterpret_cast<const float*>(sm + OFF_BIAS);
    const int r0l = 16 * rg + gr, r1l = r0l + 8;

    for (int tile = blockIdx.x; tile < NTILES; tile += gridDim.x) {
        const int row0 = tile * TILE_M;

        // ---- c0 cp.async: column-split by half so completion is WARP-LOCAL ----
        // half0: cols j0..23 (chunks 0..5);  half1: cols j24..63 (chunks 6..15)
        // rows: this warp's own 16-row group. Epilogue reads exactly this set.
        if (half == 0) {
            for (int i = l; i < 16 * 6; i += 32) {
                int r16 = i / 6, jc = i % 6;
                int r = 16 * rg + r16;
                uint32_t dst = smb + OFF_C + (uint32_t)r * 256u + ((uint32_t)(jc ^ (r & 7)) << 4);
                cpa16(dst, c0 + (size_t)(row0 + r) * 64 + jc * 4);
            }
        } else {
            for (int i = l; i < 16 * 10; i += 32) {
                int r16 = i / 10, jc = 6 + i % 10;
                int r = 16 * rg + r16;
                uint32_t dst = smb + OFF_C + (uint32_t)r * 256u + ((uint32_t)(jc ^ (r & 7)) << 4);
                cpa16(dst, c0 + (size_t)(row0 + r) * 64 + jc * 4);
            }
        }
        CP_COMMIT();

        // ---- A tile: batched LDG (MLP=16 per batch) -> split to hi/lo frags ----
        uint32_t ahi[32], alo[32];
        #pragma unroll
        for (int hb = 0; hb < 2; hb++) {               // hb=0: x (s 0..3), hb=1: h0 (s 4..7)
            const float* bp = hb ? h0 : x;
            float2 v[16];
            #pragma unroll
            for (int ss = 0; ss < 4; ss++) {           // issue all 16 loads first (deep MLP)
                int kf2 = 8 * ss + q;
                const float2* p0 = reinterpret_cast<const float2*>(bp) + (size_t)(row0 + r0l) * 32 + kf2;
                const float2* p1 = reinterpret_cast<const float2*>(bp) + (size_t)(row0 + r1l) * 32 + kf2;
                v[4 * ss + 0] = p0[0];
                v[4 * ss + 1] = p1[0];
                v[4 * ss + 2] = p0[4];
                v[4 * ss + 3] = p1[4];
            }
            #pragma unroll
            for (int ss = 0; ss < 4; ss++) {
                int s = 4 * hb + ss;
                split2(v[4 * ss + 0].x, v[4 * ss + 0].y, ahi[4 * s + 0], alo[4 * s + 0]);
                split2(v[4 * ss + 1].x, v[4 * ss + 1].y, ahi[4 * s + 1], alo[4 * s + 1]);
                split2(v[4 * ss + 2].x, v[4 * ss + 2].y, ahi[4 * s + 2], alo[4 * s + 2]);
                split2(v[4 * ss + 3].x, v[4 * ss + 3].y, ahi[4 * s + 3], alo[4 * s + 3]);
            }
        }

        // ---- warp-pair n-split: half0 = z + gates j0..23, half1 = gates j24..63 ----
        if (half == 0) {
            do_pass_z(sm, bias, ahi, alo, r0l, r1l, q, l, row0, out);
            CP_WAIT0();                 // this warp's own c0 chunks
            __syncwarp();
            do_pass_g4(8,  sm, bias, ahi, alo, r0l, r1l, q, l);
            do_pass_g4(12, sm, bias, ahi, alo, r0l, r1l, q, l);
            do_pass_g4(16, sm, bias, ahi, alo, r0l, r1l, q, l);
        } else {
            CP_WAIT0();
            __syncwarp();
            do_pass_g4(20, sm, bias, ahi, alo, r0l, r1l, q, l);
            do_pass_g4(24, sm, bias, ahi, alo, r0l, r1l, q, l);
            do_pass_g4(28, sm, bias, ahi, alo, r0l, r1l, q, l);
            do_pass_g4(32, sm, bias, ahi, alo, r0l, r1l, q, l);
            do_pass_g4(36, sm, bias, ahi, alo, r0l, r1l, q, l);
        }

        // ---- one barrier, then fully vectorized h/c stores ----
        __syncthreads();
        #pragma unroll
        for (int i = 0; i < 4; i++) {
            int p = tid + i * NTH;                     // 0..2047
            int r = p >> 4, c4 = p & 15;
            uint32_t off = (uint32_t)r * 256u + ((uint32_t)(c4 ^ (r & 7)) << 4);
            float4 hv = *reinterpret_cast<const float4*>(sm + OFF_H + off);
            float4 cv = *reinterpret_cast<const float4*>(sm + OFF_C + off);
            size_t g = (size_t)(row0 + r) * 64 + (size_t)c4 * 4;
            *reinterpret_cast<float4*>(out + (size_t)B_ROWS * 64 + g)     = hv;
            *reinterpret_cast<float4*>(out + (size_t)2 * B_ROWS * 64 + g) = cv;
        }
        __syncthreads();   // protect OFF_H/OFF_C before next tile's cp.async / writes
    }
}

extern "C" void kernel_launch(void* const* d_in, const int* in_sizes, int n_in,
                              void* d_out, int out_size) {
    (void)in_sizes; (void)n_in; (void)out_size;
    cudaFuncSetAttribute(lstm_hmma_kernel, cudaFuncAttributeMaxDynamicSharedMemorySize, SMEM_BYTES);
    lstm_hmma_kernel<<<GRID, NTH, SMEM_BYTES>>>(
        (const float*)d_in[0], (const float*)d_in[1], (const float*)d_in[2],
        (const float*)d_in[3], (const float*)d_in[4],
        (const float*)d_in[5], (const float*)d_in[6],
        (const float*)d_in[7], (const float*)d_in[8],
        (float*)d_out);
}